// round 2
// baseline (speedup 1.0000x reference)
#include <cuda_runtime.h>
#include <cuda_bf16.h>
#include <math.h>

#define N_PTS   262144
#define DIM     512
#define HID     256
#define NSEG    64
#define LN_EPS  1e-5f

#define RB      64      // rows per score block
#define KC      16      // k-chunk
#define RD      512     // rows per pooling chunk
#define MAXC    8       // pooling chunks per segment (loops if segment longer)

// scratch (static device globals; no runtime allocation)
__device__ float g_xn[(size_t)N_PTS * DIM];
__device__ float g_s[N_PTS];
__device__ float g_smax[NSEG];
__device__ float g_den[NSEG];
__device__ float g_part[(size_t)NSEG * MAXC * DIM];

// ---------------------------------------------------------------------------
// Kernel 1: LayerNorm -> g_xn.  One warp per row (512 floats = 16/lane).
// ---------------------------------------------------------------------------
__global__ __launch_bounds__(256) void ln_kernel(
    const float* __restrict__ feats,
    const float* __restrict__ lng,
    const float* __restrict__ lnb)
{
    int warp = threadIdx.x >> 5, lane = threadIdx.x & 31;
    int row  = blockIdx.x * 8 + warp;
    if (row >= N_PTS) return;

    const float4* f4 = (const float4*)(feats + (size_t)row * DIM);
    float4 v[4];
    float sum = 0.f, sq = 0.f;
#pragma unroll
    for (int i = 0; i < 4; i++) {
        v[i] = f4[lane + 32 * i];
        sum += v[i].x + v[i].y + v[i].z + v[i].w;
        sq  += v[i].x * v[i].x + v[i].y * v[i].y + v[i].z * v[i].z + v[i].w * v[i].w;
    }
#pragma unroll
    for (int m = 16; m; m >>= 1) {
        sum += __shfl_xor_sync(0xffffffffu, sum, m);
        sq  += __shfl_xor_sync(0xffffffffu, sq,  m);
    }
    float mu  = sum * (1.0f / DIM);
    float var = sq * (1.0f / DIM) - mu * mu;
    float rs  = rsqrtf(var + LN_EPS);

    const float4* g4 = (const float4*)lng;
    const float4* b4 = (const float4*)lnb;
    float4* o4 = (float4*)(g_xn + (size_t)row * DIM);
#pragma unroll
    for (int i = 0; i < 4; i++) {
        int idx = lane + 32 * i;
        float4 g = g4[idx], b = b4[idx], r;
        r.x = (v[i].x - mu) * rs * g.x + b.x;
        r.y = (v[i].y - mu) * rs * g.y + b.y;
        r.z = (v[i].z - mu) * rs * g.z + b.z;
        r.w = (v[i].w - mu) * rs * g.w + b.w;
        o4[idx] = r;
    }
}

// ---------------------------------------------------------------------------
// Kernel 2: score GEMM + GELU + w2 dot.  64 rows x 256 hid per block.
// Thread (tx in [0,16) over hid groups of 16, ty in [0,16) over row groups of 4).
// ---------------------------------------------------------------------------
__global__ __launch_bounds__(256) void score_kernel(
    const float* __restrict__ w1,
    const float* __restrict__ b1,
    const float* __restrict__ w2,
    const float* __restrict__ b2)
{
    __shared__ float ws[KC][HID];   // 16 KB, [k][j]
    __shared__ float xs[KC][RB];    // 4 KB,  [k][r]

    int tid = threadIdx.x;
    int tx = tid & 15, ty = tid >> 4;
    int row0 = blockIdx.x * RB;

    float acc[4][16];
#pragma unroll
    for (int i = 0; i < 4; i++)
#pragma unroll
        for (int j = 0; j < 16; j++) acc[i][j] = 0.f;

    for (int k0 = 0; k0 < DIM; k0 += KC) {
        // stage w1[tid][k0..k0+15] transposed into ws
        const float4* wrow = (const float4*)(w1 + (size_t)tid * DIM + k0);
        float4 a0 = wrow[0], a1 = wrow[1], a2 = wrow[2], a3 = wrow[3];
        ws[0][tid] = a0.x;  ws[1][tid] = a0.y;  ws[2][tid]  = a0.z;  ws[3][tid]  = a0.w;
        ws[4][tid] = a1.x;  ws[5][tid] = a1.y;  ws[6][tid]  = a1.z;  ws[7][tid]  = a1.w;
        ws[8][tid] = a2.x;  ws[9][tid] = a2.y;  ws[10][tid] = a2.z;  ws[11][tid] = a2.w;
        ws[12][tid] = a3.x; ws[13][tid] = a3.y; ws[14][tid] = a3.z;  ws[15][tid] = a3.w;

        // stage xn[row0..row0+63][k0..k0+15] transposed into xs
        int r  = tid >> 2;
        int kq = (tid & 3) * 4;
        float4 xv4 = *(const float4*)(g_xn + (size_t)(row0 + r) * DIM + k0 + kq);
        xs[kq + 0][r] = xv4.x; xs[kq + 1][r] = xv4.y;
        xs[kq + 2][r] = xv4.z; xs[kq + 3][r] = xv4.w;
        __syncthreads();

#pragma unroll
        for (int k = 0; k < KC; k++) {
            float4 xv = *(const float4*)&xs[k][ty * 4];
            float4 wa = *(const float4*)&ws[k][tx * 16 + 0];
            float4 wb = *(const float4*)&ws[k][tx * 16 + 4];
            float4 wc = *(const float4*)&ws[k][tx * 16 + 8];
            float4 wd = *(const float4*)&ws[k][tx * 16 + 12];
            float xr[4] = {xv.x, xv.y, xv.z, xv.w};
            float wr[16] = {wa.x, wa.y, wa.z, wa.w, wb.x, wb.y, wb.z, wb.w,
                            wc.x, wc.y, wc.z, wc.w, wd.x, wd.y, wd.z, wd.w};
#pragma unroll
            for (int i = 0; i < 4; i++)
#pragma unroll
                for (int j = 0; j < 16; j++)
                    acc[i][j] = fmaf(xr[i], wr[j], acc[i][j]);
        }
        __syncthreads();
    }

    // epilogue: + b1, exact GELU, dot with w2, reduce across tx
    float p[4] = {0.f, 0.f, 0.f, 0.f};
#pragma unroll
    for (int jj = 0; jj < 16; jj++) {
        int j = tx * 16 + jj;
        float bj  = b1[j];
        float w2j = w2[j];
#pragma unroll
        for (int i = 0; i < 4; i++) {
            float h  = acc[i][jj] + bj;
            float ge = 0.5f * h * (1.0f + erff(h * 0.70710678118654752f));
            p[i] = fmaf(w2j, ge, p[i]);
        }
    }
#pragma unroll
    for (int m = 8; m; m >>= 1)
#pragma unroll
        for (int i = 0; i < 4; i++)
            p[i] += __shfl_xor_sync(0xffffffffu, p[i], m);

    if (tx == 0) {
        float bb = b2[0];
#pragma unroll
        for (int i = 0; i < 4; i++)
            g_s[row0 + ty * 4 + i] = p[i] + bb;
    }
}

// ---------------------------------------------------------------------------
// Kernel 3: per-segment softmax stats (max, sum of exp)
// ---------------------------------------------------------------------------
__global__ __launch_bounds__(256) void stats_kernel(const int* __restrict__ off)
{
    __shared__ float red[256];
    int s = blockIdx.x;
    int lo = off[s], hi = off[s + 1];
    int tid = threadIdx.x;

    float m = -1e30f;
    for (int i = lo + tid; i < hi; i += 256) m = fmaxf(m, g_s[i]);
    red[tid] = m;
    __syncthreads();
    for (int step = 128; step; step >>= 1) {
        if (tid < step) red[tid] = fmaxf(red[tid], red[tid + step]);
        __syncthreads();
    }
    float M = red[0];
    __syncthreads();

    float sum = 0.f;
    for (int i = lo + tid; i < hi; i += 256) sum += expf(g_s[i] - M);
    red[tid] = sum;
    __syncthreads();
    for (int step = 128; step; step >>= 1) {
        if (tid < step) red[tid] += red[tid + step];
        __syncthreads();
    }
    if (tid == 0) { g_smax[s] = M; g_den[s] = red[0]; }
}

// ---------------------------------------------------------------------------
// Kernel 4: chunked weighted pooling -> deterministic partials (no atomics)
// grid = (MAXC, NSEG); block 256, thread owns 2 feature dims.
// ---------------------------------------------------------------------------
__global__ __launch_bounds__(256) void pool1_kernel(
    const float* __restrict__ feats, const int* __restrict__ off)
{
    __shared__ float wsm[RD];
    int s = blockIdx.y, c = blockIdx.x;
    int lo = off[s], hi = off[s + 1];
    int tid = threadIdx.x;

    float M   = g_smax[s];
    float inv = 1.0f / g_den[s];
    float ax = 0.f, ay = 0.f;

    for (int r0 = lo + c * RD; r0 < hi; r0 += MAXC * RD) {
        int cnt = min(RD, hi - r0);
        __syncthreads();
        for (int i = tid; i < cnt; i += 256) wsm[i] = expf(g_s[r0 + i] - M) * inv;
        __syncthreads();
#pragma unroll 4
        for (int r = 0; r < cnt; r++) {
            float w = wsm[r];
            float2 v = *(const float2*)(feats + (size_t)(r0 + r) * DIM + tid * 2);
            ax = fmaf(w, v.x, ax);
            ay = fmaf(w, v.y, ay);
        }
    }
    float* p = g_part + ((size_t)(s * MAXC + c)) * DIM;
    p[tid * 2]     = ax;
    p[tid * 2 + 1] = ay;
}

// ---------------------------------------------------------------------------
// Kernel 5: reduce partials -> out
// ---------------------------------------------------------------------------
__global__ __launch_bounds__(256) void pool2_kernel(float* __restrict__ out)
{
    int s = blockIdx.x, tid = threadIdx.x;
    float ax = 0.f, ay = 0.f;
#pragma unroll
    for (int c = 0; c < MAXC; c++) {
        const float* p = g_part + ((size_t)(s * MAXC + c)) * DIM;
        ax += p[tid * 2];
        ay += p[tid * 2 + 1];
    }
    out[s * DIM + tid * 2]     = ax;
    out[s * DIM + tid * 2 + 1] = ay;
}

// ---------------------------------------------------------------------------
extern "C" void kernel_launch(void* const* d_in, const int* in_sizes, int n_in,
                              void* d_out, int out_size)
{
    const float* feats = (const float*)d_in[0];
    const float* lng   = (const float*)d_in[1];
    const float* lnb   = (const float*)d_in[2];
    const float* w1    = (const float*)d_in[3];
    const float* b1    = (const float*)d_in[4];
    const float* w2    = (const float*)d_in[5];
    const float* b2    = (const float*)d_in[6];
    const int*   off   = (const int*)d_in[7];
    float* out = (float*)d_out;

    ln_kernel<<<N_PTS / 8, 256>>>(feats, lng, lnb);
    score_kernel<<<N_PTS / RB, 256>>>(w1, b1, w2, b2);
    stats_kernel<<<NSEG, 256>>>(off);
    dim3 g1(MAXC, NSEG);
    pool1_kernel<<<g1, 256>>>(feats, off);
    pool2_kernel<<<NSEG, 256>>>(out);
}

// round 5
// speedup vs baseline: 5.1738x; 5.1738x over previous
#include <cuda_runtime.h>
#include <cuda_bf16.h>
#include <math.h>
#include <cstdint>

#define N_PTS   262144
#define DIM     512
#define HID     256
#define NSEG    64
#define LN_EPS  1e-5f

#define MTILE   128     // rows per score CTA
#define KC      64      // K-chunk (64 bf16 = 128 B row = SW128 atom width)
#define NCHUNK  (DIM / KC)
#define RD      256     // rows per pooling chunk
#define MAXC    16      // pooling chunks per segment

// ---------------- scratch (static device globals; no runtime allocation) ----
__device__ float          g_s[N_PTS];
__device__ float          g_smax[NSEG];
__device__ float          g_den[NSEG];
__device__ float          g_part[(size_t)NSEG * MAXC * DIM];
__device__ __nv_bfloat16  g_w1hi[HID * DIM];
__device__ __nv_bfloat16  g_w1lo[HID * DIM];

// ---------------- helpers ---------------------------------------------------
__device__ __forceinline__ uint32_t smem_u32(const void* p) {
    uint32_t a;
    asm("{ .reg .u64 t; cvta.to.shared.u64 t, %1; cvt.u32.u64 %0, t; }"
        : "=r"(a) : "l"(p));
    return a;
}
#define SWZ128(o) ((o) ^ (((o) >> 3) & 0x70))

#define LDSM_X4(r, addr)                                                       \
    asm volatile("ldmatrix.sync.aligned.m8n8.x4.shared.b16 {%0,%1,%2,%3}, [%4];" \
        : "=r"((r)[0]), "=r"((r)[1]), "=r"((r)[2]), "=r"((r)[3]) : "r"(addr))

__device__ __forceinline__ void mma16816(float* d, const uint32_t* a, const uint32_t* b) {
    asm volatile(
        "mma.sync.aligned.m16n8k16.row.col.f32.bf16.bf16.f32 "
        "{%0,%1,%2,%3}, {%4,%5,%6,%7}, {%8,%9}, {%0,%1,%2,%3};"
        : "+f"(d[0]), "+f"(d[1]), "+f"(d[2]), "+f"(d[3])
        : "r"(a[0]), "r"(a[1]), "r"(a[2]), "r"(a[3]), "r"(b[0]), "r"(b[1]));
}

__device__ __forceinline__ uint32_t pack_bf2(float a, float b) {
    __nv_bfloat162 t = __floats2bfloat162_rn(a, b);
    return *(uint32_t*)&t;
}
__device__ __forceinline__ float gelu_exact(float h) {
    return 0.5f * h * (1.0f + erff(h * 0.70710678118654752f));
}

// ---------------- smem layout (bytes) for score_fused -----------------------
#define SM_MU    0        // 128 f32
#define SM_RS    512
#define SM_LNG   1024     // 512 f32
#define SM_LNB   3072
#define SM_B1    5120     // 256 f32
#define SM_W2    6144
#define SM_RED   7168     // 4 x 128 f32 (epilogue cross-warp reduce) = 2048 B
#define SM_AHI   16384    // 128 x 128B = 16 KB   (1024-aligned for SW128)
#define SM_ALO   (SM_AHI + 16384)
#define SM_BHI   (SM_ALO + 16384)   // 256 x 128B = 32 KB
#define SM_BLO   (SM_BHI + 32768)
#define SM_TOTAL (SM_BLO + 32768)   // 114688 B

// ---------------------------------------------------------------------------
// Kernel 0: convert w1 to bf16 hi/lo pair (tiny)
// ---------------------------------------------------------------------------
__global__ __launch_bounds__(256) void w1cvt_kernel(const float* __restrict__ w1)
{
    int i = (blockIdx.x * 256 + threadIdx.x) * 4;
#pragma unroll
    for (int j = 0; j < 4; j++) {
        float w = w1[i + j];
        __nv_bfloat16 hi = __float2bfloat16_rn(w);
        float lo = w - __bfloat162float(hi);
        g_w1hi[i + j] = hi;
        g_w1lo[i + j] = __float2bfloat16_rn(lo);
    }
}

// ---------------------------------------------------------------------------
// Kernel 1: fused LayerNorm + bf16-split mma.sync GEMM + GELU + w2 dot -> g_s
// 512 threads, 128 rows x 256 hid per CTA, K=512 in 8 chunks of 64.
// Warp w: rows (w&3)*32..+32, cols (w>>2)*64..+64.
// ---------------------------------------------------------------------------
__global__ __launch_bounds__(512, 1)
void score_fused(const float* __restrict__ feats,
                 const float* __restrict__ lng,
                 const float* __restrict__ lnb,
                 const float* __restrict__ b1,
                 const float* __restrict__ w2,
                 const float* __restrict__ b2)
{
    extern __shared__ char smem[];
    uint32_t sb = smem_u32(smem);
    int tid  = threadIdx.x;
    int w    = tid >> 5, lane = tid & 31;
    int rg   = w & 3,  cg = w >> 2;
    int row0 = blockIdx.x * MTILE;

    float* s_mu  = (float*)(smem + SM_MU);
    float* s_rs  = (float*)(smem + SM_RS);
    float* s_lng = (float*)(smem + SM_LNG);
    float* s_lnb = (float*)(smem + SM_LNB);
    float* s_b1  = (float*)(smem + SM_B1);
    float* s_w2  = (float*)(smem + SM_W2);
    float* s_red = (float*)(smem + SM_RED);

    for (int i = tid; i < DIM; i += 512) { s_lng[i] = lng[i]; s_lnb[i] = lnb[i]; }
    for (int i = tid; i < HID; i += 512) { s_b1[i] = b1[i]; s_w2[i] = w2[i]; }

    // --- pass 1: per-row mean / rstd (16 warps x 8 rows) ---
#pragma unroll
    for (int rr = 0; rr < 8; rr++) {
        int row = w * 8 + rr;
        const float4* f4 = (const float4*)(feats + (size_t)(row0 + row) * DIM);
        float sum = 0.f, sq = 0.f;
#pragma unroll
        for (int i = 0; i < 4; i++) {
            float4 v = f4[lane + 32 * i];
            sum += v.x + v.y + v.z + v.w;
            sq  += v.x * v.x + v.y * v.y + v.z * v.z + v.w * v.w;
        }
#pragma unroll
        for (int m = 16; m; m >>= 1) {
            sum += __shfl_xor_sync(0xffffffffu, sum, m);
            sq  += __shfl_xor_sync(0xffffffffu, sq,  m);
        }
        if (lane == 0) {
            float mu = sum * (1.0f / DIM);
            float var = sq * (1.0f / DIM) - mu * mu;
            s_mu[row] = mu;
            s_rs[row] = rsqrtf(var + LN_EPS);
        }
    }
    __syncthreads();

    // staging roles
    int arow = tid >> 2, aq = tid & 3;        // A: thread = (row, 16-col quarter)
    int brow = tid >> 1, bh = tid & 1;        // B: thread = (hid row, 32-col half)
    float amu = s_mu[arow], ars = s_rs[arow];
    const float* aft = feats + (size_t)(row0 + arow) * DIM + aq * 16;

    // ldmatrix per-lane address components
    int a_row_l   = rg * 32 + (lane & 15);
    int a_chunk   = (lane >> 4) * 16;
    int b_row_l   = cg * 64 + (lane & 7) + ((lane & 16) >> 1);
    int b_chunk   = ((lane >> 3) & 1) * 16;

    float acc[2][8][4];
#pragma unroll
    for (int rt = 0; rt < 2; rt++)
#pragma unroll
        for (int ng = 0; ng < 8; ng++)
#pragma unroll
            for (int i = 0; i < 4; i++) acc[rt][ng][i] = 0.f;

    for (int c = 0; c < NCHUNK; c++) {
        int k0 = c * KC;

        // ---- stage A: LayerNorm + hi/lo split, 128x64 bf16 each ----
        {
            const float4* fr = (const float4*)(aft + k0);
            const float4* gr = (const float4*)(s_lng + k0 + aq * 16);
            const float4* br = (const float4*)(s_lnb + k0 + aq * 16);
            float v[16];
#pragma unroll
            for (int j = 0; j < 4; j++) {
                float4 f = fr[j], g = gr[j], b = br[j];
                v[j*4+0] = (f.x - amu) * ars * g.x + b.x;
                v[j*4+1] = (f.y - amu) * ars * g.y + b.y;
                v[j*4+2] = (f.z - amu) * ars * g.z + b.z;
                v[j*4+3] = (f.w - amu) * ars * g.w + b.w;
            }
            uint4 hv[2], lv[2];
#pragma unroll
            for (int hblk = 0; hblk < 2; hblk++) {
                uint32_t* hp = (uint32_t*)&hv[hblk];
                uint32_t* lp = (uint32_t*)&lv[hblk];
#pragma unroll
                for (int p2 = 0; p2 < 4; p2++) {
                    float x0 = v[hblk*8 + p2*2], x1 = v[hblk*8 + p2*2 + 1];
                    __nv_bfloat162 hi2 = __floats2bfloat162_rn(x0, x1);
                    float l0 = x0 - __bfloat162float(hi2.x);
                    float l1 = x1 - __bfloat162float(hi2.y);
                    hp[p2] = *(uint32_t*)&hi2;
                    lp[p2] = pack_bf2(l0, l1);
                }
                uint32_t off = arow * 128 + aq * 32 + hblk * 16;
                uint32_t sw = SWZ128(off);
                *(uint4*)(smem + SM_AHI + sw) = hv[hblk];
                *(uint4*)(smem + SM_ALO + sw) = lv[hblk];
            }
        }
        // ---- stage B: copy preconverted w1 chunk, 256x64 bf16 hi/lo ----
        {
            const uint4* sh = (const uint4*)(g_w1hi + (size_t)brow * DIM + k0 + bh * 32);
            const uint4* sl = (const uint4*)(g_w1lo + (size_t)brow * DIM + k0 + bh * 32);
#pragma unroll
            for (int j = 0; j < 4; j++) {
                uint32_t off = brow * 128 + bh * 64 + j * 16;
                uint32_t sw = SWZ128(off);
                *(uint4*)(smem + SM_BHI + sw) = sh[j];
                *(uint4*)(smem + SM_BLO + sw) = sl[j];
            }
        }
        __syncthreads();

        // ---- compute: 4 k16-steps ----
#pragma unroll
        for (int ks = 0; ks < 4; ks++) {
            uint32_t ah[2][4], al[2][4];
#pragma unroll
            for (int rt = 0; rt < 2; rt++) {
                uint32_t off = (a_row_l + rt * 16) * 128 + ks * 32 + a_chunk;
                uint32_t sw = SWZ128(off);
                LDSM_X4(ah[rt], sb + SM_AHI + sw);
                LDSM_X4(al[rt], sb + SM_ALO + sw);
            }
#pragma unroll
            for (int np = 0; np < 4; np++) {
                uint32_t bhf[4], blf[4];
                uint32_t off = (b_row_l + np * 16) * 128 + ks * 32 + b_chunk;
                uint32_t sw = SWZ128(off);
                LDSM_X4(bhf, sb + SM_BHI + sw);
                LDSM_X4(blf, sb + SM_BLO + sw);
#pragma unroll
                for (int rt = 0; rt < 2; rt++)
#pragma unroll
                    for (int j = 0; j < 2; j++) {
                        float* d = acc[rt][np * 2 + j];
                        mma16816(d, ah[rt], &bhf[j * 2]);
                        mma16816(d, ah[rt], &blf[j * 2]);
                        mma16816(d, al[rt], &bhf[j * 2]);
                    }
            }
        }
        __syncthreads();
    }

    // ---- epilogue: + b1, exact GELU, dot with w2, reduce ----
    float p[2][2] = {{0.f, 0.f}, {0.f, 0.f}};
#pragma unroll
    for (int rt = 0; rt < 2; rt++)
#pragma unroll
        for (int ng = 0; ng < 8; ng++) {
            int colb = cg * 64 + ng * 8 + (lane & 3) * 2;
            float b1a = s_b1[colb], b1b = s_b1[colb + 1];
            float w2a = s_w2[colb], w2b = s_w2[colb + 1];
            p[rt][0] = fmaf(w2a, gelu_exact(acc[rt][ng][0] + b1a), p[rt][0]);
            p[rt][0] = fmaf(w2b, gelu_exact(acc[rt][ng][1] + b1b), p[rt][0]);
            p[rt][1] = fmaf(w2a, gelu_exact(acc[rt][ng][2] + b1a), p[rt][1]);
            p[rt][1] = fmaf(w2b, gelu_exact(acc[rt][ng][3] + b1b), p[rt][1]);
        }
#pragma unroll
    for (int m = 1; m <= 2; m <<= 1)
#pragma unroll
        for (int rt = 0; rt < 2; rt++)
#pragma unroll
            for (int h = 0; h < 2; h++)
                p[rt][h] += __shfl_xor_sync(0xffffffffu, p[rt][h], m);

    if ((lane & 3) == 0) {
        int rb = rg * 32 + (lane >> 2);
#pragma unroll
        for (int rt = 0; rt < 2; rt++)
#pragma unroll
            for (int h = 0; h < 2; h++)
                s_red[cg * 128 + rb + rt * 16 + h * 8] = p[rt][h];
    }
    __syncthreads();
    if (tid < MTILE) {
        float s = s_red[tid] + s_red[128 + tid] + s_red[256 + tid] + s_red[384 + tid];
        g_s[row0 + tid] = s + b2[0];
    }
}

// ---------------------------------------------------------------------------
// Kernel 2: per-segment softmax stats (max, sum of exp)
// ---------------------------------------------------------------------------
__global__ __launch_bounds__(256) void stats_kernel(const int* __restrict__ off)
{
    __shared__ float red[256];
    int s = blockIdx.x;
    int lo = off[s], hi = off[s + 1];
    int tid = threadIdx.x;

    float m = -1e30f;
    for (int i = lo + tid; i < hi; i += 256) m = fmaxf(m, g_s[i]);
    red[tid] = m;
    __syncthreads();
    for (int step = 128; step; step >>= 1) {
        if (tid < step) red[tid] = fmaxf(red[tid], red[tid + step]);
        __syncthreads();
    }
    float M = red[0];
    __syncthreads();

    float sum = 0.f;
    for (int i = lo + tid; i < hi; i += 256) sum += expf(g_s[i] - M);
    red[tid] = sum;
    __syncthreads();
    for (int step = 128; step; step >>= 1) {
        if (tid < step) red[tid] += red[tid + step];
        __syncthreads();
    }
    if (tid == 0) { g_smax[s] = M; g_den[s] = red[0]; }
}

// ---------------------------------------------------------------------------
// Kernel 3: chunked weighted pooling -> deterministic partials
// ---------------------------------------------------------------------------
__global__ __launch_bounds__(256) void pool1_kernel(
    const float* __restrict__ feats, const int* __restrict__ off)
{
    __shared__ float wsm[RD];
    int s = blockIdx.y, c = blockIdx.x;
    int lo = off[s], hi = off[s + 1];
    int tid = threadIdx.x;

    float M   = g_smax[s];
    float inv = 1.0f / g_den[s];
    float ax = 0.f, ay = 0.f, bx = 0.f, by = 0.f;

    for (int r0 = lo + c * RD; r0 < hi; r0 += MAXC * RD) {
        int cnt = min(RD, hi - r0);
        __syncthreads();
        for (int i = tid; i < cnt; i += 256) wsm[i] = expf(g_s[r0 + i] - M) * inv;
        __syncthreads();
        int r = 0;
        for (; r + 8 <= cnt; r += 8) {
#pragma unroll
            for (int u = 0; u < 8; u += 2) {
                float w0 = wsm[r + u], w1v = wsm[r + u + 1];
                float2 v0 = *(const float2*)(feats + (size_t)(r0 + r + u) * DIM + tid * 2);
                float2 v1 = *(const float2*)(feats + (size_t)(r0 + r + u + 1) * DIM + tid * 2);
                ax = fmaf(w0, v0.x, ax); ay = fmaf(w0, v0.y, ay);
                bx = fmaf(w1v, v1.x, bx); by = fmaf(w1v, v1.y, by);
            }
        }
        for (; r < cnt; r++) {
            float wv = wsm[r];
            float2 v = *(const float2*)(feats + (size_t)(r0 + r) * DIM + tid * 2);
            ax = fmaf(wv, v.x, ax); ay = fmaf(wv, v.y, ay);
        }
    }
    float* p = g_part + ((size_t)(s * MAXC + c)) * DIM;
    p[tid * 2]     = ax + bx;
    p[tid * 2 + 1] = ay + by;
}

// ---------------------------------------------------------------------------
// Kernel 4: reduce partials -> out
// ---------------------------------------------------------------------------
__global__ __launch_bounds__(256) void pool2_kernel(float* __restrict__ out)
{
    int s = blockIdx.x, tid = threadIdx.x;
    float ax = 0.f, ay = 0.f;
#pragma unroll
    for (int c = 0; c < MAXC; c++) {
        const float* p = g_part + ((size_t)(s * MAXC + c)) * DIM;
        ax += p[tid * 2];
        ay += p[tid * 2 + 1];
    }
    out[s * DIM + tid * 2]     = ax;
    out[s * DIM + tid * 2 + 1] = ay;
}

// ---------------------------------------------------------------------------
extern "C" void kernel_launch(void* const* d_in, const int* in_sizes, int n_in,
                              void* d_out, int out_size)
{
    const float* feats = (const float*)d_in[0];
    const float* lng   = (const float*)d_in[1];
    const float* lnb   = (const float*)d_in[2];
    const float* w1    = (const float*)d_in[3];
    const float* b1    = (const float*)d_in[4];
    const float* w2    = (const float*)d_in[5];
    const float* b2    = (const float*)d_in[6];
    const int*   off   = (const int*)d_in[7];
    float* out = (float*)d_out;

    static int attr_done = 0;
    if (!attr_done) {
        cudaFuncSetAttribute(score_fused, cudaFuncAttributeMaxDynamicSharedMemorySize, SM_TOTAL);
        attr_done = 1;
    }

    w1cvt_kernel<<<HID * DIM / 1024, 256>>>(w1);
    score_fused<<<N_PTS / MTILE, 512, SM_TOTAL>>>(feats, lng, lnb, b1, w2, b2);
    stats_kernel<<<NSEG, 256>>>(off);
    dim3 g1(MAXC, NSEG);
    pool1_kernel<<<g1, 256>>>(feats, off);
    pool2_kernel<<<NSEG, 256>>>(out);
}

// round 7
// speedup vs baseline: 5.3544x; 1.0349x over previous
#include <cuda_runtime.h>
#include <cuda_bf16.h>
#include <math.h>
#include <cstdint>

#define N_PTS   262144
#define DIM     512
#define HID     256
#define NSEG    64
#define LN_EPS  1e-5f

#define MTILE   128     // rows per score CTA
#define KC      64      // K-chunk (64 bf16 = 128 B row = SW128 atom width)
#define NCHUNK  (DIM / KC)
#define RD      256     // rows per pooling chunk
#define MAXC    16      // pooling chunks per segment

// ---------------- scratch (static device globals; no runtime allocation) ----
__device__ float          g_s[N_PTS];
__device__ float          g_smax[NSEG];
__device__ float          g_den[NSEG];
__device__ float          g_part[(size_t)NSEG * MAXC * DIM];
__device__ __nv_bfloat16  g_w1hi[HID * DIM];
__device__ __nv_bfloat16  g_w1lo[HID * DIM];

// ---------------- helpers ---------------------------------------------------
__device__ __forceinline__ uint32_t smem_u32(const void* p) {
    uint32_t a;
    asm("{ .reg .u64 t; cvta.to.shared.u64 t, %1; cvt.u32.u64 %0, t; }"
        : "=r"(a) : "l"(p));
    return a;
}
#define SWZ128(o) ((o) ^ (((o) >> 3) & 0x70))

#define LDSM_X4(r, addr)                                                       \
    asm volatile("ldmatrix.sync.aligned.m8n8.x4.shared.b16 {%0,%1,%2,%3}, [%4];" \
        : "=r"((r)[0]), "=r"((r)[1]), "=r"((r)[2]), "=r"((r)[3]) : "r"(addr))

#define CP_ASYNC16(dst, src)                                                   \
    asm volatile("cp.async.cg.shared.global [%0], [%1], 16;" :: "r"(dst), "l"(src))
#define CP_COMMIT() asm volatile("cp.async.commit_group;" ::: "memory")
#define CP_WAIT0()  asm volatile("cp.async.wait_group 0;" ::: "memory")

__device__ __forceinline__ void mma16816(float* d, const uint32_t* a, const uint32_t* b) {
    asm volatile(
        "mma.sync.aligned.m16n8k16.row.col.f32.bf16.bf16.f32 "
        "{%0,%1,%2,%3}, {%4,%5,%6,%7}, {%8,%9}, {%0,%1,%2,%3};"
        : "+f"(d[0]), "+f"(d[1]), "+f"(d[2]), "+f"(d[3])
        : "r"(a[0]), "r"(a[1]), "r"(a[2]), "r"(a[3]), "r"(b[0]), "r"(b[1]));
}

__device__ __forceinline__ uint32_t pack_bf2(float a, float b) {
    __nv_bfloat162 t = __floats2bfloat162_rn(a, b);
    return *(uint32_t*)&t;
}
__device__ __forceinline__ float gelu_exact(float h) {
    return 0.5f * h * (1.0f + erff(h * 0.70710678118654752f));
}

// ---------------- smem layout (bytes) for score_fused -----------------------
// params region
#define SM_MU    0        // 128 f32
#define SM_RS    512
#define SM_LNG   1024     // 512 f32
#define SM_LNB   3072
#define SM_B1    5120     // 256 f32
#define SM_W2    6144
#define SM_RED   7168     // 4 x 128 f32
// double-buffered tiles (1024-aligned for SW128)
#define SM_A     16384    // per buf: AHI 16KB + ALO 16KB ; stride 32KB ; x2
#define SM_AB_STRIDE 32768
#define SM_A_LO  16384
#define SM_B     81920    // per buf: BHI 32KB + BLO 32KB ; stride 64KB ; x2
#define SM_BB_STRIDE 65536
#define SM_B_LO  32768
#define SM_TOTAL (SM_B + 2 * SM_BB_STRIDE)   // 212992 B

// ---------------------------------------------------------------------------
// Kernel 0: convert w1 to bf16 hi/lo pair (tiny)
// ---------------------------------------------------------------------------
__global__ __launch_bounds__(256) void w1cvt_kernel(const float* __restrict__ w1)
{
    int i = (blockIdx.x * 256 + threadIdx.x) * 4;
#pragma unroll
    for (int j = 0; j < 4; j++) {
        float w = w1[i + j];
        __nv_bfloat16 hi = __float2bfloat16_rn(w);
        float lo = w - __bfloat162float(hi);
        g_w1hi[i + j] = hi;
        g_w1lo[i + j] = __float2bfloat16_rn(lo);
    }
}

// ---------------------------------------------------------------------------
// Kernel 1: fused LayerNorm + bf16-split mma.sync GEMM + GELU + w2 dot -> g_s
// 512 threads, 128 rows x 256 hid per CTA, K=512 in 8 chunks of 64.
// Double-buffered pipeline: cp.async B, reg-convert A, 1 sync per chunk.
// ---------------------------------------------------------------------------
__global__ __launch_bounds__(512, 1)
void score_fused(const float* __restrict__ feats,
                 const float* __restrict__ lng,
                 const float* __restrict__ lnb,
                 const float* __restrict__ b1,
                 const float* __restrict__ w2,
                 const float* __restrict__ b2)
{
    extern __shared__ char smem[];
    uint32_t sb = smem_u32(smem);
    int tid  = threadIdx.x;
    int w    = tid >> 5, lane = tid & 31;
    int rg   = w & 3,  cg = w >> 2;
    int row0 = blockIdx.x * MTILE;

    float* s_mu  = (float*)(smem + SM_MU);
    float* s_rs  = (float*)(smem + SM_RS);
    float* s_lng = (float*)(smem + SM_LNG);
    float* s_lnb = (float*)(smem + SM_LNB);
    float* s_b1  = (float*)(smem + SM_B1);
    float* s_w2  = (float*)(smem + SM_W2);
    float* s_red = (float*)(smem + SM_RED);

    for (int i = tid; i < DIM; i += 512) { s_lng[i] = lng[i]; s_lnb[i] = lnb[i]; }
    for (int i = tid; i < HID; i += 512) { s_b1[i] = b1[i]; s_w2[i] = w2[i]; }

    // --- pass 1: per-row mean / rstd (16 warps x 8 rows) ---
#pragma unroll
    for (int rr = 0; rr < 8; rr++) {
        int row = w * 8 + rr;
        const float4* f4 = (const float4*)(feats + (size_t)(row0 + row) * DIM);
        float sum = 0.f, sq = 0.f;
#pragma unroll
        for (int i = 0; i < 4; i++) {
            float4 v = f4[lane + 32 * i];
            sum += v.x + v.y + v.z + v.w;
            sq  += v.x * v.x + v.y * v.y + v.z * v.z + v.w * v.w;
        }
#pragma unroll
        for (int m = 16; m; m >>= 1) {
            sum += __shfl_xor_sync(0xffffffffu, sum, m);
            sq  += __shfl_xor_sync(0xffffffffu, sq,  m);
        }
        if (lane == 0) {
            float mu = sum * (1.0f / DIM);
            float var = sq * (1.0f / DIM) - mu * mu;
            s_mu[row] = mu;
            s_rs[row] = rsqrtf(var + LN_EPS);
        }
    }
    __syncthreads();

    // staging roles
    int arow = tid >> 2, aq = tid & 3;        // A: thread = (row, 16-col quarter)
    int brow = tid >> 1, bh = tid & 1;        // B: thread = (hid row, 32-col half)
    float amu = s_mu[arow], ars = s_rs[arow];
    const float* aft = feats + (size_t)(row0 + arow) * DIM + aq * 16;

    uint32_t a_sw = SWZ128((uint32_t)(arow * 128 + aq * 32));         // 16B-granule swizzle ok
    uint32_t a_sw2 = SWZ128((uint32_t)(arow * 128 + aq * 32 + 16));
    const __nv_bfloat16* bsrc_h = g_w1hi + (size_t)brow * DIM + bh * 32;
    const __nv_bfloat16* bsrc_l = g_w1lo + (size_t)brow * DIM + bh * 32;
    uint32_t b_sw[4];
#pragma unroll
    for (int j = 0; j < 4; j++) b_sw[j] = SWZ128((uint32_t)(brow * 128 + bh * 64 + j * 16));

    // ldmatrix per-lane address components
    int a_row_l = rg * 32 + (lane & 15);
    int a_chunk = (lane >> 4) * 16;
    int b_row_l = cg * 64 + (lane & 7) + ((lane & 16) >> 1);
    int b_chunk = ((lane >> 3) & 1) * 16;

    float acc[2][8][4];
#pragma unroll
    for (int rt = 0; rt < 2; rt++)
#pragma unroll
        for (int ng = 0; ng < 8; ng++)
#pragma unroll
            for (int i = 0; i < 4; i++) acc[rt][ng][i] = 0.f;

    // ---- staging lambdas (macro-style) ----
#define STAGE_B(cc, bi) do {                                                   \
        uint32_t bd = sb + SM_B + (bi) * SM_BB_STRIDE;                         \
        const __nv_bfloat16* sh_ = bsrc_h + (cc) * KC;                         \
        const __nv_bfloat16* sl_ = bsrc_l + (cc) * KC;                         \
        _Pragma("unroll")                                                      \
        for (int j = 0; j < 4; j++) {                                          \
            CP_ASYNC16(bd + b_sw[j],            sh_ + j * 8);                  \
            CP_ASYNC16(bd + SM_B_LO + b_sw[j],  sl_ + j * 8);                  \
        }                                                                      \
    } while (0)

#define STAGE_A(cc, bi) do {                                                   \
        uint32_t ad = sb + SM_A + (bi) * SM_AB_STRIDE;                         \
        const float4* fr = (const float4*)(aft + (cc) * KC);                   \
        const float4* gr = (const float4*)(s_lng + (cc) * KC + aq * 16);       \
        const float4* br = (const float4*)(s_lnb + (cc) * KC + aq * 16);       \
        _Pragma("unroll")                                                      \
        for (int hblk = 0; hblk < 2; hblk++) {                                 \
            uint32_t hp[4], lp[4];                                             \
            _Pragma("unroll")                                                  \
            for (int j = 0; j < 2; j++) {                                      \
                float4 f = fr[hblk * 2 + j], g = gr[hblk * 2 + j], b = br[hblk * 2 + j]; \
                float x0 = (f.x - amu) * ars * g.x + b.x;                      \
                float x1 = (f.y - amu) * ars * g.y + b.y;                      \
                float x2 = (f.z - amu) * ars * g.z + b.z;                      \
                float x3 = (f.w - amu) * ars * g.w + b.w;                      \
                __nv_bfloat162 h01 = __floats2bfloat162_rn(x0, x1);            \
                __nv_bfloat162 h23 = __floats2bfloat162_rn(x2, x3);            \
                hp[j * 2]     = *(uint32_t*)&h01;                              \
                hp[j * 2 + 1] = *(uint32_t*)&h23;                              \
                lp[j * 2]     = pack_bf2(x0 - __bfloat162float(h01.x),         \
                                         x1 - __bfloat162float(h01.y));        \
                lp[j * 2 + 1] = pack_bf2(x2 - __bfloat162float(h23.x),         \
                                         x3 - __bfloat162float(h23.y));        \
            }                                                                  \
            uint32_t sw = hblk ? a_sw2 : a_sw;                                 \
            *(uint4*)(smem + (ad - sb) + sw)           = *(uint4*)hp;          \
            *(uint4*)(smem + (ad - sb) + SM_A_LO + sw) = *(uint4*)lp;          \
        }                                                                      \
    } while (0)

    // ---- prologue: stage chunk 0 ----
    STAGE_B(0, 0);
    CP_COMMIT();
    STAGE_A(0, 0);
    CP_WAIT0();
    __syncthreads();

    for (int c = 0; c < NCHUNK; c++) {
        int nb = (c + 1) & 1;
        if (c + 1 < NCHUNK) {
            STAGE_B(c + 1, nb);
            CP_COMMIT();
            STAGE_A(c + 1, nb);
        }

        // ---- compute chunk c ----
        uint32_t abase = sb + SM_A + (c & 1) * SM_AB_STRIDE;
        uint32_t bbase = sb + SM_B + (c & 1) * SM_BB_STRIDE;
#pragma unroll
        for (int ks = 0; ks < 4; ks++) {
            uint32_t ah[2][4], al[2][4];
#pragma unroll
            for (int rt = 0; rt < 2; rt++) {
                uint32_t off = (a_row_l + rt * 16) * 128 + ks * 32 + a_chunk;
                uint32_t sw = SWZ128(off);
                LDSM_X4(ah[rt], abase + sw);
                LDSM_X4(al[rt], abase + SM_A_LO + sw);
            }
#pragma unroll
            for (int np = 0; np < 4; np++) {
                uint32_t bhf[4], blf[4];
                uint32_t off = (b_row_l + np * 16) * 128 + ks * 32 + b_chunk;
                uint32_t sw = SWZ128(off);
                LDSM_X4(bhf, bbase + sw);
                LDSM_X4(blf, bbase + SM_B_LO + sw);
#pragma unroll
                for (int rt = 0; rt < 2; rt++)
#pragma unroll
                    for (int j = 0; j < 2; j++) {
                        float* d = acc[rt][np * 2 + j];
                        mma16816(d, ah[rt], &bhf[j * 2]);
                        mma16816(d, ah[rt], &blf[j * 2]);
                        mma16816(d, al[rt], &bhf[j * 2]);
                    }
            }
        }
        CP_WAIT0();
        __syncthreads();
    }

    // ---- epilogue: + b1, exact GELU, dot with w2, reduce ----
    float p[2][2] = {{0.f, 0.f}, {0.f, 0.f}};
#pragma unroll
    for (int rt = 0; rt < 2; rt++)
#pragma unroll
        for (int ng = 0; ng < 8; ng++) {
            int colb = cg * 64 + ng * 8 + (lane & 3) * 2;
            float b1a = s_b1[colb], b1b = s_b1[colb + 1];
            float w2a = s_w2[colb], w2b = s_w2[colb + 1];
            p[rt][0] = fmaf(w2a, gelu_exact(acc[rt][ng][0] + b1a), p[rt][0]);
            p[rt][0] = fmaf(w2b, gelu_exact(acc[rt][ng][1] + b1b), p[rt][0]);
            p[rt][1] = fmaf(w2a, gelu_exact(acc[rt][ng][2] + b1a), p[rt][1]);
            p[rt][1] = fmaf(w2b, gelu_exact(acc[rt][ng][3] + b1b), p[rt][1]);
        }
#pragma unroll
    for (int m = 1; m <= 2; m <<= 1)
#pragma unroll
        for (int rt = 0; rt < 2; rt++)
#pragma unroll
            for (int h = 0; h < 2; h++)
                p[rt][h] += __shfl_xor_sync(0xffffffffu, p[rt][h], m);

    if ((lane & 3) == 0) {
        int rb = rg * 32 + (lane >> 2);
#pragma unroll
        for (int rt = 0; rt < 2; rt++)
#pragma unroll
            for (int h = 0; h < 2; h++)
                s_red[cg * 128 + rb + rt * 16 + h * 8] = p[rt][h];
    }
    __syncthreads();
    if (tid < MTILE) {
        float s = s_red[tid] + s_red[128 + tid] + s_red[256 + tid] + s_red[384 + tid];
        g_s[row0 + tid] = s + b2[0];
    }
}

// ---------------------------------------------------------------------------
// Kernel 2: per-segment softmax stats (max, sum of exp)
// ---------------------------------------------------------------------------
__global__ __launch_bounds__(256) void stats_kernel(const int* __restrict__ off)
{
    __shared__ float red[256];
    int s = blockIdx.x;
    int lo = off[s], hi = off[s + 1];
    int tid = threadIdx.x;

    float m = -1e30f;
    for (int i = lo + tid; i < hi; i += 256) m = fmaxf(m, g_s[i]);
    red[tid] = m;
    __syncthreads();
    for (int step = 128; step; step >>= 1) {
        if (tid < step) red[tid] = fmaxf(red[tid], red[tid + step]);
        __syncthreads();
    }
    float M = red[0];
    __syncthreads();

    float sum = 0.f;
    for (int i = lo + tid; i < hi; i += 256) sum += expf(g_s[i] - M);
    red[tid] = sum;
    __syncthreads();
    for (int step = 128; step; step >>= 1) {
        if (tid < step) red[tid] += red[tid + step];
        __syncthreads();
    }
    if (tid == 0) { g_smax[s] = M; g_den[s] = red[0]; }
}

// ---------------------------------------------------------------------------
// Kernel 3: chunked weighted pooling -> deterministic partials
// ---------------------------------------------------------------------------
__global__ __launch_bounds__(256) void pool1_kernel(
    const float* __restrict__ feats, const int* __restrict__ off)
{
    __shared__ float wsm[RD];
    int s = blockIdx.y, c = blockIdx.x;
    int lo = off[s], hi = off[s + 1];
    int tid = threadIdx.x;

    float M   = g_smax[s];
    float inv = 1.0f / g_den[s];
    float ax = 0.f, ay = 0.f, bx = 0.f, by = 0.f;

    for (int r0 = lo + c * RD; r0 < hi; r0 += MAXC * RD) {
        int cnt = min(RD, hi - r0);
        __syncthreads();
        for (int i = tid; i < cnt; i += 256) wsm[i] = expf(g_s[r0 + i] - M) * inv;
        __syncthreads();
        int r = 0;
        for (; r + 8 <= cnt; r += 8) {
#pragma unroll
            for (int u = 0; u < 8; u += 2) {
                float w0 = wsm[r + u], w1v = wsm[r + u + 1];
                float2 v0 = *(const float2*)(feats + (size_t)(r0 + r + u) * DIM + tid * 2);
                float2 v1 = *(const float2*)(feats + (size_t)(r0 + r + u + 1) * DIM + tid * 2);
                ax = fmaf(w0, v0.x, ax); ay = fmaf(w0, v0.y, ay);
                bx = fmaf(w1v, v1.x, bx); by = fmaf(w1v, v1.y, by);
            }
        }
        for (; r < cnt; r++) {
            float wv = wsm[r];
            float2 v = *(const float2*)(feats + (size_t)(r0 + r) * DIM + tid * 2);
            ax = fmaf(wv, v.x, ax); ay = fmaf(wv, v.y, ay);
        }
    }
    float* p = g_part + ((size_t)(s * MAXC + c)) * DIM;
    p[tid * 2]     = ax + bx;
    p[tid * 2 + 1] = ay + by;
}

// ---------------------------------------------------------------------------
// Kernel 4: reduce partials -> out
// ---------------------------------------------------------------------------
__global__ __launch_bounds__(256) void pool2_kernel(float* __restrict__ out)
{
    int s = blockIdx.x, tid = threadIdx.x;
    float ax = 0.f, ay = 0.f;
#pragma unroll
    for (int c = 0; c < MAXC; c++) {
        const float* p = g_part + ((size_t)(s * MAXC + c)) * DIM;
        ax += p[tid * 2];
        ay += p[tid * 2 + 1];
    }
    out[s * DIM + tid * 2]     = ax;
    out[s * DIM + tid * 2 + 1] = ay;
}

// ---------------------------------------------------------------------------
extern "C" void kernel_launch(void* const* d_in, const int* in_sizes, int n_in,
                              void* d_out, int out_size)
{
    const float* feats = (const float*)d_in[0];
    const float* lng   = (const float*)d_in[1];
    const float* lnb   = (const float*)d_in[2];
    const float* w1    = (const float*)d_in[3];
    const float* b1    = (const float*)d_in[4];
    const float* w2    = (const float*)d_in[5];
    const float* b2    = (const float*)d_in[6];
    const int*   off   = (const int*)d_in[7];
    float* out = (float*)d_out;

    static int attr_done = 0;
    if (!attr_done) {
        cudaFuncSetAttribute(score_fused, cudaFuncAttributeMaxDynamicSharedMemorySize, SM_TOTAL);
        attr_done = 1;
    }

    w1cvt_kernel<<<HID * DIM / 1024, 256>>>(w1);
    score_fused<<<N_PTS / MTILE, 512, SM_TOTAL>>>(feats, lng, lnb, b1, w2, b2);
    stats_kernel<<<NSEG, 256>>>(off);
    dim3 g1(MAXC, NSEG);
    pool1_kernel<<<g1, 256>>>(feats, off);
    pool2_kernel<<<NSEG, 256>>>(out);
}

// round 8
// speedup vs baseline: 7.1040x; 1.3268x over previous
#include <cuda_runtime.h>
#include <cuda_bf16.h>
#include <math.h>
#include <cstdint>

#define N_PTS   262144
#define DIM     512
#define HID     256
#define NSEG    64
#define LN_EPS  1e-5f

#define MTILE   128     // rows per score CTA
#define KC      64      // K-chunk (64 bf16 = 128 B row = SW128 atom width)
#define NCHUNK  (DIM / KC)
#define RD      256     // rows per pooling chunk
#define MAXC    16      // pooling chunks per segment

// ---------------- scratch (static device globals; no runtime allocation) ----
__device__ float          g_s[N_PTS];
__device__ float          g_smax[NSEG];
__device__ float          g_den[NSEG];
__device__ float          g_part[(size_t)NSEG * MAXC * DIM];
__device__ __nv_bfloat16  g_w1hi[HID * DIM];
__device__ __nv_bfloat16  g_w1lo[HID * DIM];

// ---------------- helpers ---------------------------------------------------
__device__ __forceinline__ uint32_t smem_u32(const void* p) {
    uint32_t a;
    asm("{ .reg .u64 t; cvta.to.shared.u64 t, %1; cvt.u32.u64 %0, t; }"
        : "=r"(a) : "l"(p));
    return a;
}
#define SWZ128(o) ((o) ^ (((o) >> 3) & 0x70))

#define LDSM_X4(r, addr)                                                       \
    asm volatile("ldmatrix.sync.aligned.m8n8.x4.shared.b16 {%0,%1,%2,%3}, [%4];" \
        : "=r"((r)[0]), "=r"((r)[1]), "=r"((r)[2]), "=r"((r)[3]) : "r"(addr))

#define CP_ASYNC16(dst, src)                                                   \
    asm volatile("cp.async.cg.shared.global [%0], [%1], 16;" :: "r"(dst), "l"(src))
#define CP_COMMIT() asm volatile("cp.async.commit_group;" ::: "memory")
#define CP_WAIT0()  asm volatile("cp.async.wait_group 0;" ::: "memory")
#define FENCE_ASYNC() asm volatile("fence.proxy.async.shared::cta;" ::: "memory")

__device__ __forceinline__ void mma16816(float* d, const uint32_t* a, const uint32_t* b) {
    asm volatile(
        "mma.sync.aligned.m16n8k16.row.col.f32.bf16.bf16.f32 "
        "{%0,%1,%2,%3}, {%4,%5,%6,%7}, {%8,%9}, {%0,%1,%2,%3};"
        : "+f"(d[0]), "+f"(d[1]), "+f"(d[2]), "+f"(d[3])
        : "r"(a[0]), "r"(a[1]), "r"(a[2]), "r"(a[3]), "r"(b[0]), "r"(b[1]));
}

__device__ __forceinline__ uint32_t pack_bf2(float a, float b) {
    __nv_bfloat162 t = __floats2bfloat162_rn(a, b);
    return *(uint32_t*)&t;
}
__device__ __forceinline__ float gelu_exact(float h) {
    return 0.5f * h * (1.0f + erff(h * 0.70710678118654752f));
}

// ---------------- tcgen05 helpers (only compiled on sm_103a passes) ---------
#if defined(__CUDA_ARCH_FEAT_SM103_ALL) || defined(__CUDA_ARCH_FEAT_SM100_ALL) || defined(__CUDA_ARCH_FEAT_SM101_ALL)
#define HAVE_TCGEN05 1

__device__ __forceinline__ uint32_t elect_one() {
    uint32_t p;
    asm volatile("{\n\t.reg .pred p;\n\t"
                 "elect.sync _|p, 0xFFFFFFFF;\n\t"
                 "selp.b32 %0, 1, 0, p;\n\t}" : "=r"(p));
    return p;
}
static constexpr uint64_t DESC_BASE_SW128 =
    (uint64_t(2) << 61) | (uint64_t(1) << 46) | (uint64_t(64) << 32) | (uint64_t(1) << 16);
#define MAKE_DESC(addr) (DESC_BASE_SW128 | ((uint64_t)((addr) >> 4) & 0x3FFF))

#define MBAR_INIT(a, c) \
    asm volatile("mbarrier.init.shared.b64 [%0], %1;" :: "r"(a), "r"(c) : "memory")
#define MBAR_WAIT(a, ph) do {                                                  \
    uint32_t _m = (a), _p = (ph), _d;                                          \
    asm volatile("{\n\t.reg .pred p;\n\t"                                      \
        "mbarrier.try_wait.parity.acquire.cta.shared::cta.b64 p, [%1], %2;\n\t"\
        "selp.b32 %0, 1, 0, p;\n\t}" : "=r"(_d) : "r"(_m), "r"(_p) : "memory");\
    if (!_d) {                                                                 \
        asm volatile("{\n\t.reg .pred P1;\n\t"                                 \
          "W%=:\n\t"                                                           \
          "mbarrier.try_wait.parity.acquire.cta.shared::cta.b64 P1, [%0], %1, 0x989680;\n\t" \
          "@P1 bra.uni D%=;\n\t"                                               \
          "bra.uni W%=;\n\t"                                                   \
          "D%=:\n\t}" :: "r"(_m), "r"(_p) : "memory");                         \
    } } while (0)

#define TC_ALLOC(sa, n) \
    asm volatile("tcgen05.alloc.cta_group::1.sync.aligned.shared::cta.b32 [%0], %1;" \
                 :: "r"(sa), "r"(n) : "memory")
#define TC_RELINQ() \
    asm volatile("tcgen05.relinquish_alloc_permit.cta_group::1.sync.aligned;")
#define TC_DEALLOC(t, n) \
    asm volatile("tcgen05.dealloc.cta_group::1.sync.aligned.b32 %0, %1;" :: "r"(t), "r"(n))
#define TC_COMMIT(mb) \
    asm volatile("tcgen05.commit.cta_group::1.mbarrier::arrive::one.shared::cluster.b64 [%0];" \
                 :: "r"(mb) : "memory")
#define TC_FENCE_AFTER()  asm volatile("tcgen05.fence::after_thread_sync;"  ::: "memory")
#define TC_FENCE_BEFORE() asm volatile("tcgen05.fence::before_thread_sync;" ::: "memory")
#define TC_WAIT_LD()      asm volatile("tcgen05.wait::ld.sync.aligned;" ::: "memory")

#define TC_LD_X32(r, ta)                                                       \
    asm volatile("tcgen05.ld.sync.aligned.32x32b.x32.b32 "                     \
        "{%0, %1, %2, %3, %4, %5, %6, %7, "                                    \
        " %8, %9, %10, %11, %12, %13, %14, %15, "                              \
        " %16, %17, %18, %19, %20, %21, %22, %23, "                            \
        " %24, %25, %26, %27, %28, %29, %30, %31}, [%32];"                     \
        : "=r"((r)[0]),  "=r"((r)[1]),  "=r"((r)[2]),  "=r"((r)[3]),           \
          "=r"((r)[4]),  "=r"((r)[5]),  "=r"((r)[6]),  "=r"((r)[7]),           \
          "=r"((r)[8]),  "=r"((r)[9]),  "=r"((r)[10]), "=r"((r)[11]),          \
          "=r"((r)[12]), "=r"((r)[13]), "=r"((r)[14]), "=r"((r)[15]),          \
          "=r"((r)[16]), "=r"((r)[17]), "=r"((r)[18]), "=r"((r)[19]),          \
          "=r"((r)[20]), "=r"((r)[21]), "=r"((r)[22]), "=r"((r)[23]),          \
          "=r"((r)[24]), "=r"((r)[25]), "=r"((r)[26]), "=r"((r)[27]),          \
          "=r"((r)[28]), "=r"((r)[29]), "=r"((r)[30]), "=r"((r)[31])           \
        : "r"(ta))

__device__ __forceinline__ void tc_mma_f16_ss(uint32_t d, uint64_t a, uint64_t b,
                                              uint32_t idesc, bool acc) {
    uint32_t en = acc ? 1u : 0u;
    asm volatile("{\n\t.reg .pred p;\n\t"
                 "setp.ne.u32 p, %5, 0;\n\t"
                 "tcgen05.mma.cta_group::1.kind::f16 [%0], %1, %2, %3, {%4, %4, %4, %4}, p;\n\t}"
                 :: "r"(d), "l"(a), "l"(b), "r"(idesc), "r"(0u), "r"(en)
                 : "memory");
}
// idesc: dtype=F32, a=BF16, b=BF16, N=256, M=128 (formula validated by test_mma 0x8080490)
#define TC_IDESC ((1u << 4) | (1u << 7) | (1u << 10) | ((HID / 8) << 17) | ((MTILE / 16) << 24))
#endif  // tcgen05

// ---------------- smem layout (bytes) for score_fused -----------------------
#define SM_MU    0        // 128 f32
#define SM_RS    512
#define SM_LNG   1024     // 512 f32
#define SM_LNB   3072
#define SM_B1    5120     // 256 f32
#define SM_W2    6144
#define SM_RED   7168     // 4 x 128 f32 (fallback epilogue reduce)
#define SM_TMEM  9216     // tcgen05: TMEM base ptr (4B)
#define SM_MBARB 9224     // tcgen05: mbarrier (8B)
// double-buffered tiles (1024-aligned for SW128)
#define SM_A     16384    // per buf: AHI 16KB + ALO 16KB ; stride 32KB ; x2
#define SM_AB_STRIDE 32768
#define SM_A_LO  16384
#define SM_B     81920    // per buf: BHI 32KB + BLO 32KB ; stride 64KB ; x2
#define SM_BB_STRIDE 65536
#define SM_B_LO  32768
#define SM_TOTAL (SM_B + 2 * SM_BB_STRIDE)   // 212992 B

// ---------------------------------------------------------------------------
// Kernel 0: convert w1 to bf16 hi/lo pair (tiny)
// ---------------------------------------------------------------------------
__global__ __launch_bounds__(256) void w1cvt_kernel(const float* __restrict__ w1)
{
    int i = (blockIdx.x * 256 + threadIdx.x) * 4;
#pragma unroll
    for (int j = 0; j < 4; j++) {
        float w = w1[i + j];
        __nv_bfloat16 hi = __float2bfloat16_rn(w);
        float lo = w - __bfloat162float(hi);
        g_w1hi[i + j] = hi;
        g_w1lo[i + j] = __float2bfloat16_rn(lo);
    }
}

// ---------------------------------------------------------------------------
// Kernel 1: fused LayerNorm + bf16-split GEMM + GELU + w2 dot -> g_s
// 512 threads, 128 rows x 256 hid per CTA, K=512 in 8 chunks of 64.
// tcgen05 path on sm_103a cubins; mma.sync fallback otherwise.
// ---------------------------------------------------------------------------
__global__ __launch_bounds__(512, 1)
void score_fused(const float* __restrict__ feats,
                 const float* __restrict__ lng,
                 const float* __restrict__ lnb,
                 const float* __restrict__ b1,
                 const float* __restrict__ w2,
                 const float* __restrict__ b2)
{
    extern __shared__ char smem[];
    uint32_t sb = smem_u32(smem);
    int tid  = threadIdx.x;
    int w    = tid >> 5, lane = tid & 31;
    int row0 = blockIdx.x * MTILE;

    float* s_mu  = (float*)(smem + SM_MU);
    float* s_rs  = (float*)(smem + SM_RS);
    float* s_lng = (float*)(smem + SM_LNG);
    float* s_lnb = (float*)(smem + SM_LNB);
    float* s_b1  = (float*)(smem + SM_B1);
    float* s_w2  = (float*)(smem + SM_W2);

#ifdef HAVE_TCGEN05
    if (w == 0) { TC_ALLOC(sb + SM_TMEM, 256); TC_RELINQ(); }
    if (tid == 0) MBAR_INIT(sb + SM_MBARB, 1);
#endif

    for (int i = tid; i < DIM; i += 512) { s_lng[i] = lng[i]; s_lnb[i] = lnb[i]; }
    for (int i = tid; i < HID; i += 512) { s_b1[i] = b1[i]; s_w2[i] = w2[i]; }

    // --- pass 1: per-row mean / rstd (16 warps x 8 rows) ---
#pragma unroll
    for (int rr = 0; rr < 8; rr++) {
        int row = w * 8 + rr;
        const float4* f4 = (const float4*)(feats + (size_t)(row0 + row) * DIM);
        float sum = 0.f, sq = 0.f;
#pragma unroll
        for (int i = 0; i < 4; i++) {
            float4 v = f4[lane + 32 * i];
            sum += v.x + v.y + v.z + v.w;
            sq  += v.x * v.x + v.y * v.y + v.z * v.z + v.w * v.w;
        }
#pragma unroll
        for (int m = 16; m; m >>= 1) {
            sum += __shfl_xor_sync(0xffffffffu, sum, m);
            sq  += __shfl_xor_sync(0xffffffffu, sq,  m);
        }
        if (lane == 0) {
            float mu = sum * (1.0f / DIM);
            float var = sq * (1.0f / DIM) - mu * mu;
            s_mu[row] = mu;
            s_rs[row] = rsqrtf(var + LN_EPS);
        }
    }
    __syncthreads();

    // staging roles
    int arow = tid >> 2, aq = tid & 3;        // A: thread = (row, 16-col quarter)
    int brow = tid >> 1, bh = tid & 1;        // B: thread = (hid row, 32-col half)
    float amu = s_mu[arow], ars = s_rs[arow];
    const float* aft = feats + (size_t)(row0 + arow) * DIM + aq * 16;

    uint32_t a_sw  = SWZ128((uint32_t)(arow * 128 + aq * 32));
    uint32_t a_sw2 = SWZ128((uint32_t)(arow * 128 + aq * 32 + 16));
    const __nv_bfloat16* bsrc_h = g_w1hi + (size_t)brow * DIM + bh * 32;
    const __nv_bfloat16* bsrc_l = g_w1lo + (size_t)brow * DIM + bh * 32;
    uint32_t b_sw[4];
#pragma unroll
    for (int j = 0; j < 4; j++) b_sw[j] = SWZ128((uint32_t)(brow * 128 + bh * 64 + j * 16));

#define STAGE_B(cc, bi) do {                                                   \
        uint32_t bd = sb + SM_B + (bi) * SM_BB_STRIDE;                         \
        const __nv_bfloat16* sh_ = bsrc_h + (cc) * KC;                         \
        const __nv_bfloat16* sl_ = bsrc_l + (cc) * KC;                         \
        _Pragma("unroll")                                                      \
        for (int j = 0; j < 4; j++) {                                          \
            CP_ASYNC16(bd + b_sw[j],            sh_ + j * 8);                  \
            CP_ASYNC16(bd + SM_B_LO + b_sw[j],  sl_ + j * 8);                  \
        }                                                                      \
    } while (0)

#define STAGE_A(cc, bi) do {                                                   \
        uint32_t ad = sb + SM_A + (bi) * SM_AB_STRIDE;                         \
        const float4* fr = (const float4*)(aft + (cc) * KC);                   \
        const float4* gr = (const float4*)(s_lng + (cc) * KC + aq * 16);       \
        const float4* br = (const float4*)(s_lnb + (cc) * KC + aq * 16);       \
        _Pragma("unroll")                                                      \
        for (int hblk = 0; hblk < 2; hblk++) {                                 \
            uint32_t hp[4], lp[4];                                             \
            _Pragma("unroll")                                                  \
            for (int j = 0; j < 2; j++) {                                      \
                float4 f = fr[hblk * 2 + j], g = gr[hblk * 2 + j], b = br[hblk * 2 + j]; \
                float x0 = (f.x - amu) * ars * g.x + b.x;                      \
                float x1 = (f.y - amu) * ars * g.y + b.y;                      \
                float x2 = (f.z - amu) * ars * g.z + b.z;                      \
                float x3 = (f.w - amu) * ars * g.w + b.w;                      \
                __nv_bfloat162 h01 = __floats2bfloat162_rn(x0, x1);            \
                __nv_bfloat162 h23 = __floats2bfloat162_rn(x2, x3);            \
                hp[j * 2]     = *(uint32_t*)&h01;                              \
                hp[j * 2 + 1] = *(uint32_t*)&h23;                              \
                lp[j * 2]     = pack_bf2(x0 - __bfloat162float(h01.x),         \
                                         x1 - __bfloat162float(h01.y));        \
                lp[j * 2 + 1] = pack_bf2(x2 - __bfloat162float(h23.x),         \
                                         x3 - __bfloat162float(h23.y));        \
            }                                                                  \
            uint32_t sw = hblk ? a_sw2 : a_sw;                                 \
            *(uint4*)(smem + (ad - sb) + sw)           = *(uint4*)hp;          \
            *(uint4*)(smem + (ad - sb) + SM_A_LO + sw) = *(uint4*)lp;          \
        }                                                                      \
    } while (0)

    // ---- prologue: stage chunk 0 ----
    STAGE_B(0, 0);
    CP_COMMIT();
    STAGE_A(0, 0);
    CP_WAIT0();
    FENCE_ASYNC();
    __syncthreads();

#ifdef HAVE_TCGEN05
    // ===================== tcgen05 path =====================
    uint32_t tmem;
    asm volatile("ld.shared.b32 %0, [%1];" : "=r"(tmem) : "r"(sb + SM_TMEM));

    for (int c = 0; c < NCHUNK; c++) {
        // issue 12 MMA dispatches for chunk c (buffers staged & fenced)
        if (w == 0 && elect_one()) {
            uint32_t abase = sb + SM_A + (c & 1) * SM_AB_STRIDE;
            uint32_t bbase = sb + SM_B + (c & 1) * SM_BB_STRIDE;
            uint64_t adh = MAKE_DESC(abase);
            uint64_t adl = MAKE_DESC(abase + SM_A_LO);
            uint64_t bdh = MAKE_DESC(bbase);
            uint64_t bdl = MAKE_DESC(bbase + SM_B_LO);
#pragma unroll
            for (int s = 0; s < 4; s++)
                tc_mma_f16_ss(tmem, adh + s * 2, bdh + s * 2, TC_IDESC, !(c == 0 && s == 0));
#pragma unroll
            for (int s = 0; s < 4; s++)
                tc_mma_f16_ss(tmem, adh + s * 2, bdl + s * 2, TC_IDESC, true);
#pragma unroll
            for (int s = 0; s < 4; s++)
                tc_mma_f16_ss(tmem, adl + s * 2, bdh + s * 2, TC_IDESC, true);
            TC_COMMIT(sb + SM_MBARB);
        }
        // before re-staging buffer (c+1)&1 we need MMA(c-1) (which read it) done
        if (c >= 1) MBAR_WAIT(sb + SM_MBARB, (c - 1) & 1);
        if (c + 1 < NCHUNK) {
            STAGE_B(c + 1, (c + 1) & 1);
            CP_COMMIT();
            STAGE_A(c + 1, (c + 1) & 1);
            CP_WAIT0();
            FENCE_ASYNC();
        }
        __syncthreads();
    }
    MBAR_WAIT(sb + SM_MBARB, (NCHUNK - 1) & 1);
    TC_FENCE_AFTER();

    // ---- epilogue: warps 0..3 read D (own 32-lane subpartition) ----
    if (w < 4) {
        float acc = 0.f;
#pragma unroll
        for (int cb = 0; cb < 8; cb++) {
            uint32_t r[32];
            TC_LD_X32(r, tmem + cb * 32);
            TC_WAIT_LD();
#pragma unroll
            for (int j = 0; j < 32; j++) {
                int col = cb * 32 + j;
                float h = __uint_as_float(r[j]) + s_b1[col];
                acc = fmaf(s_w2[col], gelu_exact(h), acc);
            }
        }
        TC_FENCE_BEFORE();
        g_s[row0 + w * 32 + lane] = acc + b2[0];
    }
    __syncthreads();
    if (w == 0) TC_DEALLOC(tmem, 256);

#else
    // ===================== mma.sync fallback =====================
    int rg = w & 3, cg = w >> 2;
    float* s_red = (float*)(smem + SM_RED);

    int a_row_l = rg * 32 + (lane & 15);
    int a_chunk = (lane >> 4) * 16;
    int b_row_l = cg * 64 + (lane & 7) + ((lane & 16) >> 1);
    int b_chunk = ((lane >> 3) & 1) * 16;

    float acc[2][8][4];
#pragma unroll
    for (int rt = 0; rt < 2; rt++)
#pragma unroll
        for (int ng = 0; ng < 8; ng++)
#pragma unroll
            for (int i = 0; i < 4; i++) acc[rt][ng][i] = 0.f;

    for (int c = 0; c < NCHUNK; c++) {
        int nb = (c + 1) & 1;
        if (c + 1 < NCHUNK) {
            STAGE_B(c + 1, nb);
            CP_COMMIT();
            STAGE_A(c + 1, nb);
        }
        uint32_t abase = sb + SM_A + (c & 1) * SM_AB_STRIDE;
        uint32_t bbase = sb + SM_B + (c & 1) * SM_BB_STRIDE;
#pragma unroll
        for (int ks = 0; ks < 4; ks++) {
            uint32_t ah[2][4], al[2][4];
#pragma unroll
            for (int rt = 0; rt < 2; rt++) {
                uint32_t off = (a_row_l + rt * 16) * 128 + ks * 32 + a_chunk;
                uint32_t sw = SWZ128(off);
                LDSM_X4(ah[rt], abase + sw);
                LDSM_X4(al[rt], abase + SM_A_LO + sw);
            }
#pragma unroll
            for (int np = 0; np < 4; np++) {
                uint32_t bhf[4], blf[4];
                uint32_t off = (b_row_l + np * 16) * 128 + ks * 32 + b_chunk;
                uint32_t sw = SWZ128(off);
                LDSM_X4(bhf, bbase + sw);
                LDSM_X4(blf, bbase + SM_B_LO + sw);
#pragma unroll
                for (int rt = 0; rt < 2; rt++)
#pragma unroll
                    for (int j = 0; j < 2; j++) {
                        float* d = acc[rt][np * 2 + j];
                        mma16816(d, ah[rt], &bhf[j * 2]);
                        mma16816(d, ah[rt], &blf[j * 2]);
                        mma16816(d, al[rt], &bhf[j * 2]);
                    }
            }
        }
        CP_WAIT0();
        __syncthreads();
    }

    float p[2][2] = {{0.f, 0.f}, {0.f, 0.f}};
#pragma unroll
    for (int rt = 0; rt < 2; rt++)
#pragma unroll
        for (int ng = 0; ng < 8; ng++) {
            int colb = cg * 64 + ng * 8 + (lane & 3) * 2;
            float b1a = s_b1[colb], b1b = s_b1[colb + 1];
            float w2a = s_w2[colb], w2b = s_w2[colb + 1];
            p[rt][0] = fmaf(w2a, gelu_exact(acc[rt][ng][0] + b1a), p[rt][0]);
            p[rt][0] = fmaf(w2b, gelu_exact(acc[rt][ng][1] + b1b), p[rt][0]);
            p[rt][1] = fmaf(w2a, gelu_exact(acc[rt][ng][2] + b1a), p[rt][1]);
            p[rt][1] = fmaf(w2b, gelu_exact(acc[rt][ng][3] + b1b), p[rt][1]);
        }
#pragma unroll
    for (int m = 1; m <= 2; m <<= 1)
#pragma unroll
        for (int rt = 0; rt < 2; rt++)
#pragma unroll
            for (int h = 0; h < 2; h++)
                p[rt][h] += __shfl_xor_sync(0xffffffffu, p[rt][h], m);

    if ((lane & 3) == 0) {
        int rb = rg * 32 + (lane >> 2);
#pragma unroll
        for (int rt = 0; rt < 2; rt++)
#pragma unroll
            for (int h = 0; h < 2; h++)
                s_red[cg * 128 + rb + rt * 16 + h * 8] = p[rt][h];
    }
    __syncthreads();
    if (tid < MTILE) {
        float s = s_red[tid] + s_red[128 + tid] + s_red[256 + tid] + s_red[384 + tid];
        g_s[row0 + tid] = s + b2[0];
    }
#endif
}

// ---------------------------------------------------------------------------
// Kernel 2: per-segment softmax stats (max, sum of exp)
// ---------------------------------------------------------------------------
__global__ __launch_bounds__(256) void stats_kernel(const int* __restrict__ off)
{
    __shared__ float red[256];
    int s = blockIdx.x;
    int lo = off[s], hi = off[s + 1];
    int tid = threadIdx.x;

    float m = -1e30f;
    for (int i = lo + tid; i < hi; i += 256) m = fmaxf(m, g_s[i]);
    red[tid] = m;
    __syncthreads();
    for (int step = 128; step; step >>= 1) {
        if (tid < step) red[tid] = fmaxf(red[tid], red[tid + step]);
        __syncthreads();
    }
    float M = red[0];
    __syncthreads();

    float sum = 0.f;
    for (int i = lo + tid; i < hi; i += 256) sum += expf(g_s[i] - M);
    red[tid] = sum;
    __syncthreads();
    for (int step = 128; step; step >>= 1) {
        if (tid < step) red[tid] += red[tid + step];
        __syncthreads();
    }
    if (tid == 0) { g_smax[s] = M; g_den[s] = red[0]; }
}

// ---------------------------------------------------------------------------
// Kernel 3: chunked weighted pooling -> deterministic partials
// ---------------------------------------------------------------------------
__global__ __launch_bounds__(256) void pool1_kernel(
    const float* __restrict__ feats, const int* __restrict__ off)
{
    __shared__ float wsm[RD];
    int s = blockIdx.y, c = blockIdx.x;
    int lo = off[s], hi = off[s + 1];
    int tid = threadIdx.x;

    float M   = g_smax[s];
    float inv = 1.0f / g_den[s];
    float ax = 0.f, ay = 0.f, bx = 0.f, by = 0.f;

    for (int r0 = lo + c * RD; r0 < hi; r0 += MAXC * RD) {
        int cnt = min(RD, hi - r0);
        __syncthreads();
        for (int i = tid; i < cnt; i += 256) wsm[i] = expf(g_s[r0 + i] - M) * inv;
        __syncthreads();
        int r = 0;
        for (; r + 8 <= cnt; r += 8) {
#pragma unroll
            for (int u = 0; u < 8; u += 2) {
                float w0 = wsm[r + u], w1v = wsm[r + u + 1];
                float2 v0 = *(const float2*)(feats + (size_t)(r0 + r + u) * DIM + tid * 2);
                float2 v1 = *(const float2*)(feats + (size_t)(r0 + r + u + 1) * DIM + tid * 2);
                ax = fmaf(w0, v0.x, ax); ay = fmaf(w0, v0.y, ay);
                bx = fmaf(w1v, v1.x, bx); by = fmaf(w1v, v1.y, by);
            }
        }
        for (; r < cnt; r++) {
            float wv = wsm[r];
            float2 v = *(const float2*)(feats + (size_t)(r0 + r) * DIM + tid * 2);
            ax = fmaf(wv, v.x, ax); ay = fmaf(wv, v.y, ay);
        }
    }
    float* p = g_part + ((size_t)(s * MAXC + c)) * DIM;
    p[tid * 2]     = ax + bx;
    p[tid * 2 + 1] = ay + by;
}

// ---------------------------------------------------------------------------
// Kernel 4: reduce partials -> out
// ---------------------------------------------------------------------------
__global__ __launch_bounds__(256) void pool2_kernel(float* __restrict__ out)
{
    int s = blockIdx.x, tid = threadIdx.x;
    float ax = 0.f, ay = 0.f;
#pragma unroll
    for (int c = 0; c < MAXC; c++) {
        const float* p = g_part + ((size_t)(s * MAXC + c)) * DIM;
        ax += p[tid * 2];
        ay += p[tid * 2 + 1];
    }
    out[s * DIM + tid * 2]     = ax;
    out[s * DIM + tid * 2 + 1] = ay;
}

// ---------------------------------------------------------------------------
extern "C" void kernel_launch(void* const* d_in, const int* in_sizes, int n_in,
                              void* d_out, int out_size)
{
    const float* feats = (const float*)d_in[0];
    const float* lng   = (const float*)d_in[1];
    const float* lnb   = (const float*)d_in[2];
    const float* w1    = (const float*)d_in[3];
    const float* b1    = (const float*)d_in[4];
    const float* w2    = (const float*)d_in[5];
    const float* b2    = (const float*)d_in[6];
    const int*   off   = (const int*)d_in[7];
    float* out = (float*)d_out;

    static int attr_done = 0;
    if (!attr_done) {
        cudaFuncSetAttribute(score_fused, cudaFuncAttributeMaxDynamicSharedMemorySize, SM_TOTAL);
        attr_done = 1;
    }

    w1cvt_kernel<<<HID * DIM / 1024, 256>>>(w1);
    score_fused<<<N_PTS / MTILE, 512, SM_TOTAL>>>(feats, lng, lnb, b1, w2, b2);
    stats_kernel<<<NSEG, 256>>>(off);
    dim3 g1(MAXC, NSEG);
    pool1_kernel<<<g1, 256>>>(feats, off);
    pool2_kernel<<<NSEG, 256>>>(out);
}